// round 15
// baseline (speedup 1.0000x reference)
#include <cuda_runtime.h>
#include <cuda_bf16.h>
#include <cstdint>

#define NN      50000
#define NGRAPH  64
#define HID     128
#define NLAYERS 4
#define CAP     192     // per-node in-edge capacity (max expected in-degree ~45)
#define NSUB    16      // pool sub-slices per graph

// bf16 GEMM smem layout
#define BFRAG_PER_W (8 * 16 * 32)          // 4096 uint4 (8 k16-blocks)
#define SAB 68                              // A row stride in uint: banks 4g+t, conflict-free
#define SMEM_GEMM (BFRAG_PER_W * 16 + 128 * SAB * 4)   // 100352

#define PACK_BLKS  ((5 * BFRAG_PER_W + 255) / 256)     // 80
#define ZERO_BLKS  ((NN + 255) / 256)                  // 196

// ---------------- scratch (no allocations allowed) ----------------
__device__ __nv_bfloat162 g_tb[NN * (HID / 2)];  // bf16 messages (h @ W)
__device__ __nv_bfloat162 g_ab[NN * (HID / 2)];  // bf16 activations (pre-act)
__device__ int      g_srcs[NN * CAP];   // bucketed in-edge source lists
__device__ float    g_w[NN * CAP];      // precomputed per-edge norm weights
__device__ int      g_cursor[NN];       // in-degree (w/o self loop)
__device__ uint4    g_Bfrag[5 * BFRAG_PER_W];  // fragment-packed bf16 hi/lo weights
__device__ float    g_pooled[NGRAPH * HID];
__device__ float    g_cnt[NGRAPH];
__device__ float    g_zero_bias[HID];   // stays all-zero
__device__ int      g_idx64;            // 1 if index buffers are int64

// ---------------- bf16 helpers -----------------------------------
__device__ __forceinline__ uint32_t pack_bf16x2(float lo_val, float hi_val) {
    __nv_bfloat162 h = __floats2bfloat162_rn(lo_val, hi_val);
    return *(uint32_t*)&h;
}
__device__ __forceinline__ float2 unpack_bf16x2(uint32_t u) {
    return __bfloat1622float2(*(__nv_bfloat162*)&u);
}
__device__ __forceinline__ void mma_bf16(
    float& c0, float& c1, float& c2, float& c3,
    uint32_t a0, uint32_t a1, uint32_t a2, uint32_t a3,
    uint32_t b0, uint32_t b1)
{
    asm volatile(
        "mma.sync.aligned.m16n8k16.row.col.f32.bf16.bf16.f32 "
        "{%0,%1,%2,%3}, {%4,%5,%6,%7}, {%8,%9}, {%0,%1,%2,%3};"
        : "+f"(c0), "+f"(c1), "+f"(c2), "+f"(c3)
        : "r"(a0), "r"(a1), "r"(a2), "r"(a3), "r"(b0), "r"(b1));
}

// ---------------- weight pack (stream B) -------------------------
__global__ void pack_kernel(const float* __restrict__ W_in,
                            const float* __restrict__ conv_W) {
    int i = blockIdx.x * blockDim.x + threadIdx.x;
    if (i >= 5 * BFRAG_PER_W) return;
    int lane = i & 31;
    int jn   = (i >> 5) & 15;
    int kb   = (i >> 9) & 7;
    int w    = i >> 12;
    int t = lane & 3, g = lane >> 2;
    const float* W = (w == 0) ? W_in : conv_W + (size_t)(w - 1) * HID * HID;
    const int n = jn * 8 + g;
    const int k0 = kb * 16;
    float w00 = W[(k0 + 2 * t) * HID + n];
    float w01 = W[(k0 + 2 * t + 1) * HID + n];
    float w10 = W[(k0 + 2 * t + 8) * HID + n];
    float w11 = W[(k0 + 2 * t + 9) * HID + n];
    float h00 = __bfloat162float(__float2bfloat16_rn(w00));
    float h01 = __bfloat162float(__float2bfloat16_rn(w01));
    float h10 = __bfloat162float(__float2bfloat16_rn(w10));
    float h11 = __bfloat162float(__float2bfloat16_rn(w11));
    g_Bfrag[i] = make_uint4(pack_bf16x2(h00, h01), pack_bf16x2(h10, h11),
                            pack_bf16x2(w00 - h00, w01 - h01),
                            pack_bf16x2(w10 - h10, w11 - h11));
}

// ---------------- zero + dtype detect (stream A) -----------------
__global__ void zero_detect_kernel(const int* __restrict__ e) {
    const int bid = blockIdx.x;
    const int tid = threadIdx.x;
    if (bid < ZERO_BLKS) {
        int i = bid * 256 + tid;
        if (i < NN) g_cursor[i] = 0;
        if (i < NGRAPH * HID) g_pooled[i] = 0.0f;
    } else {
        if (tid < 32) {
            int nz = 0;
            if (e[1 + 2 * tid] != 0) nz = 1;
            if (e[1 + 2 * (tid + 32)] != 0) nz = 1;
            unsigned m = __ballot_sync(0xFFFFFFFFu, nz);
            if (tid == 0) g_idx64 = (m == 0u) ? 1 : 0;
        }
    }
}

// ---------------- adjacency build --------------------------------
__global__ void fill_kernel(const void* __restrict__ eidx, int E) {
    const int is64 = g_idx64;
    int i = blockIdx.x * blockDim.x + threadIdx.x;
    if (i < E) {
        int s, t;
        if (is64) {
            s = (int)((const long long*)eidx)[i];
            t = (int)((const long long*)eidx)[(long long)E + i];
        } else {
            s = ((const int*)eidx)[i];
            t = ((const int*)eidx)[E + i];
        }
        int p = atomicAdd(&g_cursor[t], 1);
        if (p < CAP) g_srcs[t * CAP + p] = s;
    }
}

// ---- per-edge weights, once: g_w[n*CAP+j] = dinv[src]*dinv[n] ----
__global__ __launch_bounds__(256) void edge_w_kernel(int N) {
    const int n = (int)((blockIdx.x * blockDim.x + threadIdx.x) >> 5);
    if (n >= N) return;
    const int lane = threadIdx.x & 31;
    const int cnt = min(g_cursor[n], CAP);
    const float dn = rsqrtf((float)cnt + 1.0f);
    for (int j = lane; j < cnt; j += 32) {
        int s = g_srcs[n * CAP + j];
        g_w[n * CAP + j] = rsqrtf((float)min(g_cursor[s], CAP) + 1.0f) * dn;
    }
}

// ---------------- bf16 tensor-core GEMM (A bf16/fp32, W hi+lo bf16) ------
// 256 threads = 8 warps (4M x 2N), warp tile 32x64. 2 CTAs/SM.
template<bool PRO, bool ABF16>
__global__ __launch_bounds__(256, 2) void gemm_kernel(
    const void* Aptr, int widx,
    const float* __restrict__ pro_bias, const float* __restrict__ epi_bias,
    __nv_bfloat162* __restrict__ outB, int M)
{
    extern __shared__ uint4 smem_u4[];
    uint4* Bs = smem_u4;                              // [8][16][32] uint4
    uint32_t* As = (uint32_t*)(smem_u4 + BFRAG_PER_W);// [128][SAB] bf16x2

    const int tid = threadIdx.x;
    const int row0 = blockIdx.x * 128;

    {
        const uint4* src = g_Bfrag + (size_t)widx * BFRAG_PER_W;
#pragma unroll
        for (int l = 0; l < BFRAG_PER_W / 256; l++)
            Bs[tid + l * 256] = src[tid + l * 256];
    }
    if (ABF16) {
        const uint4* A4 = (const uint4*)Aptr;
#pragma unroll
        for (int l = 0; l < 8; l++) {
            int f = tid + l * 256;
            int r = f >> 4;
            int c4 = f & 15;
            int grow = row0 + r;
            uint4 u = make_uint4(0, 0, 0, 0);
            if (grow < M) {
                u = A4[(size_t)grow * 16 + c4];
                if (PRO) {
                    const float4 b0 = ((const float4*)pro_bias)[c4 * 2];
                    const float4 b1 = ((const float4*)pro_bias)[c4 * 2 + 1];
                    float2 p;
                    p = unpack_bf16x2(u.x);
                    u.x = pack_bf16x2(fmaxf(p.x + b0.x, 0.f), fmaxf(p.y + b0.y, 0.f));
                    p = unpack_bf16x2(u.y);
                    u.y = pack_bf16x2(fmaxf(p.x + b0.z, 0.f), fmaxf(p.y + b0.w, 0.f));
                    p = unpack_bf16x2(u.z);
                    u.z = pack_bf16x2(fmaxf(p.x + b1.x, 0.f), fmaxf(p.y + b1.y, 0.f));
                    p = unpack_bf16x2(u.w);
                    u.w = pack_bf16x2(fmaxf(p.x + b1.z, 0.f), fmaxf(p.y + b1.w, 0.f));
                }
            }
            uint32_t* dst = &As[r * SAB + c4 * 4];
            dst[0] = u.x; dst[1] = u.y; dst[2] = u.z; dst[3] = u.w;
        }
    } else {
        const float* A = (const float*)Aptr;
#pragma unroll
        for (int l = 0; l < 16; l++) {
            int f = tid + l * 256;
            int r = f >> 5;
            int c4 = f & 31;
            int grow = row0 + r;
            float4 v = make_float4(0.f, 0.f, 0.f, 0.f);
            if (grow < M)
                v = *(const float4*)&A[(size_t)grow * 128 + c4 * 4];
            As[r * SAB + c4 * 2]     = pack_bf16x2(v.x, v.y);
            As[r * SAB + c4 * 2 + 1] = pack_bf16x2(v.z, v.w);
        }
    }
    __syncthreads();

    const int warp = tid >> 5;
    const int lane = tid & 31;
    const int g = lane >> 2;
    const int t = lane & 3;
    const int wm = (warp >> 1) * 32;
    const int jnb = (warp & 1) * 8;

    float C[2][8][4];
#pragma unroll
    for (int i = 0; i < 2; i++)
#pragma unroll
        for (int j = 0; j < 8; j++)
#pragma unroll
            for (int q = 0; q < 4; q++) C[i][j][q] = 0.0f;

#pragma unroll
    for (int kb = 0; kb < 8; kb++) {
        uint32_t a[2][4];
#pragma unroll
        for (int i = 0; i < 2; i++) {
            const int rb = wm + i * 16;
            a[i][0] = As[(rb + g) * SAB + kb * 8 + t];
            a[i][1] = As[(rb + 8 + g) * SAB + kb * 8 + t];
            a[i][2] = As[(rb + g) * SAB + kb * 8 + t + 4];
            a[i][3] = As[(rb + 8 + g) * SAB + kb * 8 + t + 4];
        }
#pragma unroll
        for (int j = 0; j < 8; j++) {
            uint4 bf = Bs[(kb * 16 + jnb + j) * 32 + lane];
#pragma unroll
            for (int i = 0; i < 2; i++) {
                mma_bf16(C[i][j][0], C[i][j][1], C[i][j][2], C[i][j][3],
                         a[i][0], a[i][1], a[i][2], a[i][3], bf.x, bf.y);
                mma_bf16(C[i][j][0], C[i][j][1], C[i][j][2], C[i][j][3],
                         a[i][0], a[i][1], a[i][2], a[i][3], bf.z, bf.w);
            }
        }
    }

#pragma unroll
    for (int i = 0; i < 2; i++) {
#pragma unroll
        for (int j = 0; j < 8; j++) {
            const int col = (jnb + j) * 8 + 2 * t;
            float be0 = 0.f, be1 = 0.f;
            if (epi_bias) { be0 = epi_bias[col]; be1 = epi_bias[col + 1]; }
            const int r0 = row0 + wm + i * 16 + g;
            const int r1 = r0 + 8;
            if (r0 < M)
                outB[(size_t)r0 * (HID / 2) + (col >> 1)] =
                    __float22bfloat162_rn(make_float2(C[i][j][0] + be0, C[i][j][1] + be1));
            if (r1 < M)
                outB[(size_t)r1 * (HID / 2) + (col >> 1)] =
                    __float22bfloat162_rn(make_float2(C[i][j][2] + be0, C[i][j][3] + be1));
        }
    }
}

// ---------------- pull aggregation: warp = node, 2 edges in parallel -----
__device__ __forceinline__ void unpack8(uint4 u, float* f) {
    float2 t0 = __bfloat1622float2(*(__nv_bfloat162*)&u.x);
    float2 t1 = __bfloat1622float2(*(__nv_bfloat162*)&u.y);
    float2 t2 = __bfloat1622float2(*(__nv_bfloat162*)&u.z);
    float2 t3 = __bfloat1622float2(*(__nv_bfloat162*)&u.w);
    f[0] = t0.x; f[1] = t0.y; f[2] = t1.x; f[3] = t1.y;
    f[4] = t2.x; f[5] = t2.y; f[6] = t3.x; f[7] = t3.y;
}

__global__ __launch_bounds__(256) void gather_kernel(int N) {
    const int n = (int)((blockIdx.x * blockDim.x + threadIdx.x) >> 5);
    if (n >= N) return;
    const int lane = threadIdx.x & 31;
    const int half = lane >> 4;
    const int fl = lane & 15;
    const uint4* __restrict__ T4 = (const uint4*)g_tb;

    const int cnt = min(g_cursor[n], CAP);
    const float dn = rsqrtf((float)cnt + 1.0f);

    float acc[8];
    {
        uint4 u = __ldg(&T4[(size_t)n * 16 + fl]);
        float f[8]; unpack8(u, f);
        const float s2 = half ? 0.0f : dn * dn;
#pragma unroll
        for (int k = 0; k < 8; k++) acc[k] = f[k] * s2;
    }

    const int base = n * CAP;
    for (int j0 = 0; j0 < cnt; j0 += 32) {
        const int m = min(32, cnt - j0);
        int   s_l = 0;
        float w_l = 0.f;
        if (lane < m) {
            s_l = g_srcs[base + j0 + lane];
            w_l = g_w[base + j0 + lane];
        }
        const int npairs4 = ((((m + 1) >> 1) + 3) & ~3);
        for (int p = 0; p < npairs4; p += 4) {
            int ia = 2 * p + half;
            int ib = ia + 2, ic = ia + 4, id = ia + 6;
            int   sa = __shfl_sync(0xFFFFFFFFu, s_l, ia);
            int   sb = __shfl_sync(0xFFFFFFFFu, s_l, ib);
            int   sc = __shfl_sync(0xFFFFFFFFu, s_l, ic);
            int   sd = __shfl_sync(0xFFFFFFFFu, s_l, id);
            float na = __shfl_sync(0xFFFFFFFFu, w_l, ia);
            float nb = __shfl_sync(0xFFFFFFFFu, w_l, ib);
            float nc = __shfl_sync(0xFFFFFFFFu, w_l, ic);
            float nd = __shfl_sync(0xFFFFFFFFu, w_l, id);
            uint4 ua = __ldg(&T4[(size_t)sa * 16 + fl]);
            uint4 ub = __ldg(&T4[(size_t)sb * 16 + fl]);
            uint4 uc = __ldg(&T4[(size_t)sc * 16 + fl]);
            uint4 ud = __ldg(&T4[(size_t)sd * 16 + fl]);
            float fa[8], fb[8], fc[8], fd[8];
            unpack8(ua, fa); unpack8(ub, fb); unpack8(uc, fc); unpack8(ud, fd);
#pragma unroll
            for (int k = 0; k < 8; k++) {
                acc[k] = fmaf(na, fa[k], acc[k]);
                acc[k] = fmaf(nb, fb[k], acc[k]);
                acc[k] = fmaf(nc, fc[k], acc[k]);
                acc[k] = fmaf(nd, fd[k], acc[k]);
            }
        }
    }

#pragma unroll
    for (int k = 0; k < 8; k++)
        acc[k] += __shfl_xor_sync(0xFFFFFFFFu, acc[k], 16);

    uint2 o;
    if (half) {
        o.x = pack_bf16x2(acc[4], acc[5]);
        o.y = pack_bf16x2(acc[6], acc[7]);
    } else {
        o.x = pack_bf16x2(acc[0], acc[1]);
        o.y = pack_bf16x2(acc[2], acc[3]);
    }
    ((uint2*)g_ab)[(size_t)n * 32 + fl * 2 + half] = o;
}

// ---------------- mean pool, 2-stage (batch sorted), fused bias+relu -----
__device__ __forceinline__ int lower_bound_batch(const void* batch, int n, int val, int is64) {
    int lo = 0, hi = n;
    while (lo < hi) {
        int mid = (lo + hi) >> 1;
        long long b = is64 ? ((const long long*)batch)[mid]
                           : (long long)((const int*)batch)[mid];
        if (b < val) lo = mid + 1; else hi = mid;
    }
    return lo;
}

__global__ void pool_partial_kernel(const void* __restrict__ batch,
                                    const float* __restrict__ bias, int n) {
    const int g = blockIdx.x;
    const int sub = blockIdx.y;
    const int tid = threadIdx.x;
    __shared__ int slo, shi;
    if (tid == 0) {
        int is64 = g_idx64;
        slo = lower_bound_batch(batch, n, g, is64);
        shi = lower_bound_batch(batch, n, g + 1, is64);
    }
    __syncthreads();
    const float b = bias[tid];
    const __nv_bfloat16* __restrict__ ab = (const __nv_bfloat16*)g_ab;
    const int lo = slo, hi = shi;
    float s0 = 0.f, s1 = 0.f;
    int r = lo + sub;
    for (; r + NSUB < hi; r += 2 * NSUB) {
        s0 += fmaxf(__bfloat162float(ab[(size_t)r * HID + tid]) + b, 0.0f);
        s1 += fmaxf(__bfloat162float(ab[(size_t)(r + NSUB) * HID + tid]) + b, 0.0f);
    }
    if (r < hi)
        s0 += fmaxf(__bfloat162float(ab[(size_t)r * HID + tid]) + b, 0.0f);
    atomicAdd(&g_pooled[g * HID + tid], s0 + s1);
    if (sub == 0 && tid == 0) g_cnt[g] = (float)(hi - lo);
}

// ---------------- heads (divide pooled sum by count here) ----------------
__global__ void heads_kernel(
    const float* __restrict__ Wd, const float* __restrict__ bd,
    const float* __restrict__ Ws, const float* __restrict__ bsn,
    const float* __restrict__ Wr, const float* __restrict__ br,
    float* __restrict__ out)
{
    const int g = blockIdx.x;
    const int head = blockIdx.y;
    const int j = threadIdx.x;
    __shared__ float p[HID];
    const float inv = 1.0f / fmaxf(g_cnt[g], 1.0f);
    p[j] = g_pooled[g * HID + j] * inv;
    __syncthreads();

    const float* W = (head == 0) ? Wd : (head == 1) ? Ws : Wr;
    const float* b = (head == 0) ? bd : (head == 1) ? bsn : br;
    float s = b[j];
#pragma unroll 8
    for (int k = 0; k < HID; k++)
        s = fmaf(p[k], W[k * HID + j], s);
    out[(size_t)head * NGRAPH * HID + g * HID + j] = s;
}

// ---------------- launch --------------------------------------------------
extern "C" void kernel_launch(void* const* d_in, const int* in_sizes, int n_in,
                              void* d_out, int out_size)
{
    const float* x      = (const float*)d_in[0];
    const void*  eidx   = d_in[1];
    const void*  batch  = d_in[2];
    const float* W_in   = (const float*)d_in[3];
    const float* b_in   = (const float*)d_in[4];
    const float* conv_W = (const float*)d_in[5];
    const float* conv_b = (const float*)d_in[6];
    const float* W_def  = (const float*)d_in[7];
    const float* b_def  = (const float*)d_in[8];
    const float* W_syn  = (const float*)d_in[9];
    const float* b_syn  = (const float*)d_in[10];
    const float* W_rel  = (const float*)d_in[11];
    const float* b_rel  = (const float*)d_in[12];
    float* out = (float*)d_out;

    const int N = in_sizes[0] / HID;       // 50000
    const int E = in_sizes[1] / 2;         // 640000

    void *pab, *ptb, *pz;
    cudaGetSymbolAddress(&pab, g_ab);
    cudaGetSymbolAddress(&ptb, g_tb);
    cudaGetSymbolAddress(&pz, g_zero_bias);
    __nv_bfloat162* ab_buf = (__nv_bfloat162*)pab;
    __nv_bfloat162* tb_buf = (__nv_bfloat162*)ptb;
    const float* zero_b = (const float*)pz;

    // one-time host-side setup (first call is the correctness run, NOT the
    // graph-capture call, so stream/event creation never happens in capture)
    static cudaStream_t sB = nullptr;
    static cudaEvent_t evFork = nullptr, evJoin = nullptr;
    if (!sB) {
        cudaFuncSetAttribute((const void*)gemm_kernel<false, false>,
                             cudaFuncAttributeMaxDynamicSharedMemorySize, SMEM_GEMM);
        cudaFuncSetAttribute((const void*)gemm_kernel<true, true>,
                             cudaFuncAttributeMaxDynamicSharedMemorySize, SMEM_GEMM);
        cudaStreamCreateWithFlags(&sB, cudaStreamNonBlocking);
        cudaEventCreateWithFlags(&evFork, cudaEventDisableTiming);
        cudaEventCreateWithFlags(&evJoin, cudaEventDisableTiming);
    }

    const int T = 256;
    const int GB = (N + 127) / 128;
    const int GW = (N * 32 + T - 1) / T;   // warp-per-node grids

    // ---- fork: stream B handles weight pack + input GEMM + conv GEMM l0 ----
    cudaEventRecord(evFork, 0);
    cudaStreamWaitEvent(sB, evFork, 0);

    // stream B chain: pack -> input GEMM -> conv GEMM (layer 0)
    pack_kernel<<<PACK_BLKS, T, 0, sB>>>(W_in, conv_W);
    gemm_kernel<false, false><<<GB, T, SMEM_GEMM, sB>>>(
        x, 0, nullptr, b_in, ab_buf, N);
    gemm_kernel<true, true><<<GB, T, SMEM_GEMM, sB>>>(
        ab_buf, 1, zero_b, nullptr, tb_buf, N);

    // stream A (default) chain: zero+detect -> fill -> edge weights
    zero_detect_kernel<<<ZERO_BLKS + 1, T>>>((const int*)eidx);
    fill_kernel<<<(E + T - 1) / T, T>>>(eidx, E);
    edge_w_kernel<<<GW, T>>>(N);

    // ---- join: gather l0 needs conv GEMM (B) and edge weights (A) ----
    cudaEventRecord(evJoin, sB);
    cudaStreamWaitEvent(0, evJoin, 0);

    gather_kernel<<<GW, T>>>(N);

    // remaining layers, serial on default stream
    for (int l = 1; l < NLAYERS; l++) {
        gemm_kernel<true, true><<<GB, T, SMEM_GEMM>>>(
            ab_buf, 1 + l, conv_b + (size_t)(l - 1) * HID, nullptr, tb_buf, N);
        gather_kernel<<<GW, T>>>(N);
    }

    // global mean pool (2-stage, fused final bias+relu)
    pool_partial_kernel<<<dim3(NGRAPH, NSUB), HID>>>(
        batch, conv_b + (size_t)(NLAYERS - 1) * HID, N);

    // output heads
    heads_kernel<<<dim3(NGRAPH, 3), HID>>>(W_def, b_def, W_syn, b_syn,
                                           W_rel, b_rel, out);
}

// round 17
// speedup vs baseline: 1.0125x; 1.0125x over previous
#include <cuda_runtime.h>
#include <cuda_bf16.h>
#include <cstdint>

#define NN      50000
#define NGRAPH  64
#define HID     128
#define NLAYERS 4
#define CAP     192     // per-node in-edge capacity (max expected in-degree ~45)
#define NSUB    16      // pool sub-slices per graph

// bf16 GEMM smem layout
#define BFRAG_PER_W (8 * 16 * 32)          // 4096 uint4 (8 k16-blocks)
#define SAB 68                              // A row stride in uint: banks 4g+t, conflict-free
#define SMEM_GEMM (BFRAG_PER_W * 16 + 128 * SAB * 4)   // 100352

#define PACK_BLKS  ((5 * BFRAG_PER_W + 255) / 256)     // 80
#define ZERO_BLKS  ((NN + 255) / 256)                  // 196
#define SETUP_BLKS (PACK_BLKS + ZERO_BLKS + 1)

// ---------------- scratch (no allocations allowed) ----------------
__device__ __nv_bfloat162 g_tb[NN * (HID / 2)];  // bf16 messages (h @ W)
__device__ __nv_bfloat162 g_ab[NN * (HID / 2)];  // bf16 activations (pre-act)
__device__ int      g_srcs[NN * CAP];   // bucketed in-edge source lists
__device__ float    g_w[NN * CAP];      // precomputed per-edge norm weights
__device__ int      g_cursor[NN];       // in-degree (w/o self loop)
__device__ uint4    g_Bfrag[5 * BFRAG_PER_W];  // fragment-packed bf16 hi/lo weights
__device__ float    g_pooled[NGRAPH * HID];
__device__ float    g_cnt[NGRAPH];
__device__ float    g_zero_bias[HID];   // stays all-zero
__device__ int      g_idx64;            // 1 if index buffers are int64

// ---------------- bf16 helpers -----------------------------------
__device__ __forceinline__ uint32_t pack_bf16x2(float lo_val, float hi_val) {
    __nv_bfloat162 h = __floats2bfloat162_rn(lo_val, hi_val);
    return *(uint32_t*)&h;
}
__device__ __forceinline__ float2 unpack_bf16x2(uint32_t u) {
    return __bfloat1622float2(*(__nv_bfloat162*)&u);
}
__device__ __forceinline__ void mma_bf16(
    float& c0, float& c1, float& c2, float& c3,
    uint32_t a0, uint32_t a1, uint32_t a2, uint32_t a3,
    uint32_t b0, uint32_t b1)
{
    asm volatile(
        "mma.sync.aligned.m16n8k16.row.col.f32.bf16.bf16.f32 "
        "{%0,%1,%2,%3}, {%4,%5,%6,%7}, {%8,%9}, {%0,%1,%2,%3};"
        : "+f"(c0), "+f"(c1), "+f"(c2), "+f"(c3)
        : "r"(a0), "r"(a1), "r"(a2), "r"(a3), "r"(b0), "r"(b1));
}
__device__ __forceinline__ void ldmatrix_x4(
    uint32_t& r0, uint32_t& r1, uint32_t& r2, uint32_t& r3, uint32_t addr)
{
    asm volatile(
        "ldmatrix.sync.aligned.m8n8.x4.shared.b16 {%0,%1,%2,%3}, [%4];"
        : "=r"(r0), "=r"(r1), "=r"(r2), "=r"(r3) : "r"(addr));
}
__device__ __forceinline__ uint32_t smem_u32(const void* p) {
    uint32_t a;
    asm("{ .reg .u64 t; cvta.to.shared.u64 t, %1; cvt.u32.u64 %0, t; }"
        : "=r"(a) : "l"(p));
    return a;
}

// ---------------- fused setup: pack B + zero cursors/pooled + detect -----
__global__ void setup_kernel(const float* __restrict__ W_in,
                             const float* __restrict__ conv_W,
                             const int* __restrict__ e) {
    const int bid = blockIdx.x;
    const int tid = threadIdx.x;
    if (bid < PACK_BLKS) {
        int i = bid * 256 + tid;
        if (i >= 5 * BFRAG_PER_W) return;
        int lane = i & 31;
        int jn   = (i >> 5) & 15;
        int kb   = (i >> 9) & 7;
        int w    = i >> 12;
        int t = lane & 3, g = lane >> 2;
        const float* W = (w == 0) ? W_in : conv_W + (size_t)(w - 1) * HID * HID;
        const int n = jn * 8 + g;
        const int k0 = kb * 16;
        float w00 = W[(k0 + 2 * t) * HID + n];
        float w01 = W[(k0 + 2 * t + 1) * HID + n];
        float w10 = W[(k0 + 2 * t + 8) * HID + n];
        float w11 = W[(k0 + 2 * t + 9) * HID + n];
        float h00 = __bfloat162float(__float2bfloat16_rn(w00));
        float h01 = __bfloat162float(__float2bfloat16_rn(w01));
        float h10 = __bfloat162float(__float2bfloat16_rn(w10));
        float h11 = __bfloat162float(__float2bfloat16_rn(w11));
        g_Bfrag[i] = make_uint4(pack_bf16x2(h00, h01), pack_bf16x2(h10, h11),
                                pack_bf16x2(w00 - h00, w01 - h01),
                                pack_bf16x2(w10 - h10, w11 - h11));
    } else if (bid < PACK_BLKS + ZERO_BLKS) {
        int i = (bid - PACK_BLKS) * 256 + tid;
        if (i < NN) g_cursor[i] = 0;
        if (i < NGRAPH * HID) g_pooled[i] = 0.0f;
    } else {
        if (tid < 32) {
            int nz = 0;
            if (e[1 + 2 * tid] != 0) nz = 1;
            if (e[1 + 2 * (tid + 32)] != 0) nz = 1;
            unsigned m = __ballot_sync(0xFFFFFFFFu, nz);
            if (tid == 0) g_idx64 = (m == 0u) ? 1 : 0;
        }
    }
}

// ---------------- adjacency build --------------------------------
__global__ void fill_kernel(const void* __restrict__ eidx, int E) {
    const int is64 = g_idx64;
    int i = blockIdx.x * blockDim.x + threadIdx.x;
    if (i < E) {
        int s, t;
        if (is64) {
            s = (int)((const long long*)eidx)[i];
            t = (int)((const long long*)eidx)[(long long)E + i];
        } else {
            s = ((const int*)eidx)[i];
            t = ((const int*)eidx)[E + i];
        }
        int p = atomicAdd(&g_cursor[t], 1);
        if (p < CAP) g_srcs[t * CAP + p] = s;
    }
}

// ---- per-edge weights, once: g_w[n*CAP+j] = dinv[src]*dinv[n] ----
__global__ __launch_bounds__(256) void edge_w_kernel(int N) {
    const int n = (int)((blockIdx.x * blockDim.x + threadIdx.x) >> 5);
    if (n >= N) return;
    const int lane = threadIdx.x & 31;
    const int cnt = min(g_cursor[n], CAP);
    const float dn = rsqrtf((float)cnt + 1.0f);
    for (int j = lane; j < cnt; j += 32) {
        int s = g_srcs[n * CAP + j];
        g_w[n * CAP + j] = rsqrtf((float)min(g_cursor[s], CAP) + 1.0f) * dn;
    }
}

// ---------------- bf16 tensor-core GEMM, tall-skinny warp tiles ----------
// outB[M,128](bf16) = op(A)[M,128] @ W[128,128] (+ epi_bias)
//   PRO:   op(a)[r][c] = relu(a[r][c] + pro_bias[c])
//   ABF16: A is bf16 (g_ab); else fp32
// 256 threads = 8 warps; warp tile M=128, N=16 (warp owns n-blocks 2w, 2w+1).
// B smem traffic per kb per warp: 2 LDS.128 for 32 MMAs. A via ldmatrix.x4.
template<bool PRO, bool ABF16>
__global__ __launch_bounds__(256, 2) void gemm_kernel(
    const void* Aptr, int widx,
    const float* __restrict__ pro_bias, const float* __restrict__ epi_bias,
    __nv_bfloat162* __restrict__ outB, int M)
{
    extern __shared__ uint4 smem_u4[];
    uint4* Bs = smem_u4;                              // [8][16][32] uint4
    uint32_t* As = (uint32_t*)(smem_u4 + BFRAG_PER_W);// [128][SAB] bf16x2

    const int tid = threadIdx.x;
    const int row0 = blockIdx.x * 128;

    // ---- load packed B frags (64KB) ----
    {
        const uint4* src = g_Bfrag + (size_t)widx * BFRAG_PER_W;
#pragma unroll
        for (int l = 0; l < BFRAG_PER_W / 256; l++)
            Bs[tid + l * 256] = src[tid + l * 256];
    }
    // ---- load A tile (optional fused bias+relu) into bf16x2 smem ----
    if (ABF16) {
        const uint4* A4 = (const uint4*)Aptr;
#pragma unroll
        for (int l = 0; l < 8; l++) {
            int f = tid + l * 256;
            int r = f >> 4;
            int c4 = f & 15;
            int grow = row0 + r;
            uint4 u = make_uint4(0, 0, 0, 0);
            if (grow < M) {
                u = A4[(size_t)grow * 16 + c4];
                if (PRO) {
                    const float4 b0 = ((const float4*)pro_bias)[c4 * 2];
                    const float4 b1 = ((const float4*)pro_bias)[c4 * 2 + 1];
                    float2 p;
                    p = unpack_bf16x2(u.x);
                    u.x = pack_bf16x2(fmaxf(p.x + b0.x, 0.f), fmaxf(p.y + b0.y, 0.f));
                    p = unpack_bf16x2(u.y);
                    u.y = pack_bf16x2(fmaxf(p.x + b0.z, 0.f), fmaxf(p.y + b0.w, 0.f));
                    p = unpack_bf16x2(u.z);
                    u.z = pack_bf16x2(fmaxf(p.x + b1.x, 0.f), fmaxf(p.y + b1.y, 0.f));
                    p = unpack_bf16x2(u.w);
                    u.w = pack_bf16x2(fmaxf(p.x + b1.z, 0.f), fmaxf(p.y + b1.w, 0.f));
                }
            }
            uint32_t* dst = &As[r * SAB + c4 * 4];
            dst[0] = u.x; dst[1] = u.y; dst[2] = u.z; dst[3] = u.w;
        }
    } else {
        const float* A = (const float*)Aptr;
#pragma unroll
        for (int l = 0; l < 16; l++) {
            int f = tid + l * 256;
            int r = f >> 5;
            int c4 = f & 31;
            int grow = row0 + r;
            float4 v = make_float4(0.f, 0.f, 0.f, 0.f);
            if (grow < M)
                v = *(const float4*)&A[(size_t)grow * 128 + c4 * 4];
            As[r * SAB + c4 * 2]     = pack_bf16x2(v.x, v.y);
            As[r * SAB + c4 * 2 + 1] = pack_bf16x2(v.z, v.w);
        }
    }
    __syncthreads();

    const int warp = tid >> 5;
    const int lane = tid & 31;
    const int g = lane >> 2;
    const int t = lane & 3;
    const int jn0 = warp * 2;          // warp's two n-blocks

    // ldmatrix lane address pattern: lanes 0-7 rows 0-7 k0; 8-15 rows 8-15 k0;
    // 16-23 rows 0-7 k8; 24-31 rows 8-15 k8  (byte col = (lane>>4)*16)
    const uint32_t as_base = smem_u32(As);
    const int lm_row = lane & 15;
    const int lm_koff = (lane >> 4) * 16;   // bytes

    float C[8][2][4];
#pragma unroll
    for (int i = 0; i < 8; i++)
#pragma unroll
        for (int j = 0; j < 2; j++)
#pragma unroll
            for (int q = 0; q < 4; q++) C[i][j][q] = 0.0f;

#pragma unroll
    for (int kb = 0; kb < 8; kb++) {
        uint32_t a[8][4];
#pragma unroll
        for (int i = 0; i < 8; i++) {
            uint32_t addr = as_base
                + (uint32_t)((i * 16 + lm_row) * (SAB * 4) + kb * 32 + lm_koff);
            ldmatrix_x4(a[i][0], a[i][1], a[i][2], a[i][3], addr);
        }
        uint4 b0 = Bs[(kb * 16 + jn0) * 32 + lane];
        uint4 b1 = Bs[(kb * 16 + jn0 + 1) * 32 + lane];
#pragma unroll
        for (int i = 0; i < 8; i++) {
            mma_bf16(C[i][0][0], C[i][0][1], C[i][0][2], C[i][0][3],
                     a[i][0], a[i][1], a[i][2], a[i][3], b0.x, b0.y);
            mma_bf16(C[i][0][0], C[i][0][1], C[i][0][2], C[i][0][3],
                     a[i][0], a[i][1], a[i][2], a[i][3], b0.z, b0.w);
            mma_bf16(C[i][1][0], C[i][1][1], C[i][1][2], C[i][1][3],
                     a[i][0], a[i][1], a[i][2], a[i][3], b1.x, b1.y);
            mma_bf16(C[i][1][0], C[i][1][1], C[i][1][2], C[i][1][3],
                     a[i][0], a[i][1], a[i][2], a[i][3], b1.z, b1.w);
        }
    }

    // ---- epilogue: bf16x2 out (+ optional bias) ----
    float be[2][2];
#pragma unroll
    for (int j = 0; j < 2; j++) {
        int col = (jn0 + j) * 8 + 2 * t;
        be[j][0] = epi_bias ? epi_bias[col] : 0.f;
        be[j][1] = epi_bias ? epi_bias[col + 1] : 0.f;
    }
#pragma unroll
    for (int i = 0; i < 8; i++) {
        const int r0 = row0 + i * 16 + g;
        const int r1 = r0 + 8;
#pragma unroll
        for (int j = 0; j < 2; j++) {
            const int col = (jn0 + j) * 8 + 2 * t;
            if (r0 < M)
                outB[(size_t)r0 * (HID / 2) + (col >> 1)] =
                    __float22bfloat162_rn(make_float2(C[i][j][0] + be[j][0],
                                                      C[i][j][1] + be[j][1]));
            if (r1 < M)
                outB[(size_t)r1 * (HID / 2) + (col >> 1)] =
                    __float22bfloat162_rn(make_float2(C[i][j][2] + be[j][0],
                                                      C[i][j][3] + be[j][1]));
        }
    }
}

// ---------------- pull aggregation: warp = node, 2 edges in parallel -----
__device__ __forceinline__ void unpack8(uint4 u, float* f) {
    float2 t0 = __bfloat1622float2(*(__nv_bfloat162*)&u.x);
    float2 t1 = __bfloat1622float2(*(__nv_bfloat162*)&u.y);
    float2 t2 = __bfloat1622float2(*(__nv_bfloat162*)&u.z);
    float2 t3 = __bfloat1622float2(*(__nv_bfloat162*)&u.w);
    f[0] = t0.x; f[1] = t0.y; f[2] = t1.x; f[3] = t1.y;
    f[4] = t2.x; f[5] = t2.y; f[6] = t3.x; f[7] = t3.y;
}

__global__ __launch_bounds__(256) void gather_kernel(int N) {
    const int n = (int)((blockIdx.x * blockDim.x + threadIdx.x) >> 5);
    if (n >= N) return;
    const int lane = threadIdx.x & 31;
    const int half = lane >> 4;
    const int fl = lane & 15;
    const uint4* __restrict__ T4 = (const uint4*)g_tb;

    const int cnt = min(g_cursor[n], CAP);
    const float dn = rsqrtf((float)cnt + 1.0f);

    float acc[8];
    {
        uint4 u = __ldg(&T4[(size_t)n * 16 + fl]);
        float f[8]; unpack8(u, f);
        const float s2 = half ? 0.0f : dn * dn;
#pragma unroll
        for (int k = 0; k < 8; k++) acc[k] = f[k] * s2;
    }

    const int base = n * CAP;
    for (int j0 = 0; j0 < cnt; j0 += 32) {
        const int m = min(32, cnt - j0);
        int   s_l = 0;
        float w_l = 0.f;
        if (lane < m) {
            s_l = g_srcs[base + j0 + lane];
            w_l = g_w[base + j0 + lane];
        }
        const int npairs4 = ((((m + 1) >> 1) + 3) & ~3);
        for (int p = 0; p < npairs4; p += 4) {
            int ia = 2 * p + half;
            int ib = ia + 2, ic = ia + 4, id = ia + 6;
            int   sa = __shfl_sync(0xFFFFFFFFu, s_l, ia);
            int   sb = __shfl_sync(0xFFFFFFFFu, s_l, ib);
            int   sc = __shfl_sync(0xFFFFFFFFu, s_l, ic);
            int   sd = __shfl_sync(0xFFFFFFFFu, s_l, id);
            float na = __shfl_sync(0xFFFFFFFFu, w_l, ia);
            float nb = __shfl_sync(0xFFFFFFFFu, w_l, ib);
            float nc = __shfl_sync(0xFFFFFFFFu, w_l, ic);
            float nd = __shfl_sync(0xFFFFFFFFu, w_l, id);
            uint4 ua = __ldg(&T4[(size_t)sa * 16 + fl]);
            uint4 ub = __ldg(&T4[(size_t)sb * 16 + fl]);
            uint4 uc = __ldg(&T4[(size_t)sc * 16 + fl]);
            uint4 ud = __ldg(&T4[(size_t)sd * 16 + fl]);
            float fa[8], fb[8], fc[8], fd[8];
            unpack8(ua, fa); unpack8(ub, fb); unpack8(uc, fc); unpack8(ud, fd);
#pragma unroll
            for (int k = 0; k < 8; k++) {
                acc[k] = fmaf(na, fa[k], acc[k]);
                acc[k] = fmaf(nb, fb[k], acc[k]);
                acc[k] = fmaf(nc, fc[k], acc[k]);
                acc[k] = fmaf(nd, fd[k], acc[k]);
            }
        }
    }

#pragma unroll
    for (int k = 0; k < 8; k++)
        acc[k] += __shfl_xor_sync(0xFFFFFFFFu, acc[k], 16);

    uint2 o;
    if (half) {
        o.x = pack_bf16x2(acc[4], acc[5]);
        o.y = pack_bf16x2(acc[6], acc[7]);
    } else {
        o.x = pack_bf16x2(acc[0], acc[1]);
        o.y = pack_bf16x2(acc[2], acc[3]);
    }
    ((uint2*)g_ab)[(size_t)n * 32 + fl * 2 + half] = o;
}

// ---------------- mean pool, 2-stage (batch sorted), fused bias+relu -----
__device__ __forceinline__ int lower_bound_batch(const void* batch, int n, int val, int is64) {
    int lo = 0, hi = n;
    while (lo < hi) {
        int mid = (lo + hi) >> 1;
        long long b = is64 ? ((const long long*)batch)[mid]
                           : (long long)((const int*)batch)[mid];
        if (b < val) lo = mid + 1; else hi = mid;
    }
    return lo;
}

__global__ void pool_partial_kernel(const void* __restrict__ batch,
                                    const float* __restrict__ bias, int n) {
    const int g = blockIdx.x;
    const int sub = blockIdx.y;
    const int tid = threadIdx.x;
    __shared__ int slo, shi;
    if (tid == 0) {
        int is64 = g_idx64;
        slo = lower_bound_batch(batch, n, g, is64);
        shi = lower_bound_batch(batch, n, g + 1, is64);
    }
    __syncthreads();
    const float b = bias[tid];
    const __nv_bfloat16* __restrict__ ab = (const __nv_bfloat16*)g_ab;
    const int lo = slo, hi = shi;
    float s0 = 0.f, s1 = 0.f;
    int r = lo + sub;
    for (; r + NSUB < hi; r += 2 * NSUB) {
        s0 += fmaxf(__bfloat162float(ab[(size_t)r * HID + tid]) + b, 0.0f);
        s1 += fmaxf(__bfloat162float(ab[(size_t)(r + NSUB) * HID + tid]) + b, 0.0f);
    }
    if (r < hi)
        s0 += fmaxf(__bfloat162float(ab[(size_t)r * HID + tid]) + b, 0.0f);
    atomicAdd(&g_pooled[g * HID + tid], s0 + s1);
    if (sub == 0 && tid == 0) g_cnt[g] = (float)(hi - lo);
}

// ---------------- heads (divide pooled sum by count here) ----------------
__global__ void heads_kernel(
    const float* __restrict__ Wd, const float* __restrict__ bd,
    const float* __restrict__ Ws, const float* __restrict__ bsn,
    const float* __restrict__ Wr, const float* __restrict__ br,
    float* __restrict__ out)
{
    const int g = blockIdx.x;
    const int head = blockIdx.y;
    const int j = threadIdx.x;
    __shared__ float p[HID];
    const float inv = 1.0f / fmaxf(g_cnt[g], 1.0f);
    p[j] = g_pooled[g * HID + j] * inv;
    __syncthreads();

    const float* W = (head == 0) ? Wd : (head == 1) ? Ws : Wr;
    const float* b = (head == 0) ? bd : (head == 1) ? bsn : br;
    float s = b[j];
#pragma unroll 8
    for (int k = 0; k < HID; k++)
        s = fmaf(p[k], W[k * HID + j], s);
    out[(size_t)head * NGRAPH * HID + g * HID + j] = s;
}

// ---------------- launch --------------------------------------------------
extern "C" void kernel_launch(void* const* d_in, const int* in_sizes, int n_in,
                              void* d_out, int out_size)
{
    const float* x      = (const float*)d_in[0];
    const void*  eidx   = d_in[1];
    const void*  batch  = d_in[2];
    const float* W_in   = (const float*)d_in[3];
    const float* b_in   = (const float*)d_in[4];
    const float* conv_W = (const float*)d_in[5];
    const float* conv_b = (const float*)d_in[6];
    const float* W_def  = (const float*)d_in[7];
    const float* b_def  = (const float*)d_in[8];
    const float* W_syn  = (const float*)d_in[9];
    const float* b_syn  = (const float*)d_in[10];
    const float* W_rel  = (const float*)d_in[11];
    const float* b_rel  = (const float*)d_in[12];
    float* out = (float*)d_out;

    const int N = in_sizes[0] / HID;       // 50000
    const int E = in_sizes[1] / 2;         // 640000

    void *pab, *ptb, *pz;
    cudaGetSymbolAddress(&pab, g_ab);
    cudaGetSymbolAddress(&ptb, g_tb);
    cudaGetSymbolAddress(&pz, g_zero_bias);
    __nv_bfloat162* ab_buf = (__nv_bfloat162*)pab;
    __nv_bfloat162* tb_buf = (__nv_bfloat162*)ptb;
    const float* zero_b = (const float*)pz;

    static int smem_set = 0;
    if (!smem_set) {
        cudaFuncSetAttribute((const void*)gemm_kernel<false, false>,
                             cudaFuncAttributeMaxDynamicSharedMemorySize, SMEM_GEMM);
        cudaFuncSetAttribute((const void*)gemm_kernel<true, true>,
                             cudaFuncAttributeMaxDynamicSharedMemorySize, SMEM_GEMM);
        smem_set = 1;
    }

    const int T = 256;
    const int GB = (N + 127) / 128;
    const int GW = (N * 32 + T - 1) / T;   // warp-per-node grids

    // 0. fused setup: pack weights + zero cursors/pooled + dtype detect
    setup_kernel<<<SETUP_BLKS, T>>>(W_in, conv_W, (const int*)eidx);

    // 1. adjacency build
    fill_kernel<<<(E + T - 1) / T, T>>>(eidx, E);
    edge_w_kernel<<<GW, T>>>(N);

    // 2. input layer: ab = bf16(x @ W_in + b_in)  (pre-activation)
    gemm_kernel<false, false><<<GB, T, SMEM_GEMM>>>(
        x, 0, nullptr, b_in, ab_buf, N);

    // 3. GCN layers: GEMM (relu+bias fused, bf16 in/out) then pull-gather
    for (int l = 0; l < NLAYERS; l++) {
        const float* pro_b = (l == 0) ? zero_b : conv_b + (size_t)(l - 1) * HID;
        gemm_kernel<true, true><<<GB, T, SMEM_GEMM>>>(
            ab_buf, 1 + l, pro_b, nullptr, tb_buf, N);
        gather_kernel<<<GW, T>>>(N);
    }

    // 4. global mean pool (2-stage, fused final bias+relu)
    pool_partial_kernel<<<dim3(NGRAPH, NSUB), HID>>>(
        batch, conv_b + (size_t)(NLAYERS - 1) * HID, N);

    // 5. output heads
    heads_kernel<<<dim3(NGRAPH, 3), HID>>>(W_def, b_def, W_syn, b_syn,
                                           W_rel, b_rel, out);
}